// round 1
// baseline (speedup 1.0000x reference)
#include <cuda_runtime.h>

// out[r, c] = x[r, c] * weight[c]   for x: [32768, 1024] fp32, weight: [1024] fp32
//
// Pure HBM-streaming kernel: 128 MiB in + 128 MiB out. float4 vectorized,
// 4 float4 per thread (MLP=4+ hides DRAM latency / TLB walk).
// Weight is 4 KiB -> L1-resident; indexed per-float4 as (idx & 255) since
// each row is exactly 256 float4.

static constexpr int ROWS = 32768;
static constexpr int COLS = 1024;
static constexpr long long N_ELEMS = (long long)ROWS * COLS;        // 33,554,432
static constexpr long long N_VEC4  = N_ELEMS / 4;                   // 8,388,608
static constexpr int THREADS = 256;
static constexpr int VEC_PER_THREAD = 4;
static constexpr int BLOCKS = (int)(N_VEC4 / (THREADS * VEC_PER_THREAD)); // 8192
static constexpr int COLS_VEC4 = COLS / 4;                          // 256

__global__ __launch_bounds__(THREADS)
void diag_weight_kernel(const float4* __restrict__ x,
                        const float4* __restrict__ w,
                        float4* __restrict__ out) {
    // Each block handles a contiguous span of THREADS*VEC_PER_THREAD float4s,
    // strided by THREADS within the block so lanes stay coalesced.
    long long base = (long long)blockIdx.x * (THREADS * VEC_PER_THREAD) + threadIdx.x;

    float4 vx[VEC_PER_THREAD];
    float4 vw[VEC_PER_THREAD];

    // Front-batch all loads (maximize MLP before any dependent use).
#pragma unroll
    for (int i = 0; i < VEC_PER_THREAD; i++) {
        long long idx = base + (long long)i * THREADS;
        vx[i] = x[idx];
        vw[i] = w[(int)(idx & (COLS_VEC4 - 1))];  // 4 KiB weight: L1 hit
    }

#pragma unroll
    for (int i = 0; i < VEC_PER_THREAD; i++) {
        long long idx = base + (long long)i * THREADS;
        float4 r;
        r.x = vx[i].x * vw[i].x;
        r.y = vx[i].y * vw[i].y;
        r.z = vx[i].z * vw[i].z;
        r.w = vx[i].w * vw[i].w;
        out[idx] = r;
    }
}

extern "C" void kernel_launch(void* const* d_in, const int* in_sizes, int n_in,
                              void* d_out, int out_size) {
    const float4* x = (const float4*)d_in[0];     // [32768, 1024] fp32
    const float4* w = (const float4*)d_in[1];     // [1024] fp32
    float4* out = (float4*)d_out;

    diag_weight_kernel<<<BLOCKS, THREADS>>>(x, w, out);
}

// round 2
// speedup vs baseline: 1.0331x; 1.0331x over previous
#include <cuda_runtime.h>

// out[r, c] = x[r, c] * weight[c]   for x: [32768, 1024] fp32, weight: [1024] fp32
//
// Pure HBM-streaming kernel: 128 MiB in + 128 MiB out, zero reuse of x/out.
// - 8 float4 per thread, all loads front-batched -> MLP_p1 = 8 per warp.
// - weight vector hoisted: with THREADS=256 and stride-256 unroll,
//   (idx & 255) == threadIdx.x for every iteration -> ONE w load per thread.
// - __ldcs / __stcs: streaming (evict-first) hints; x and out are touched
//   exactly once and the 256 MB working set can't fit 126 MB L2 anyway.

static constexpr int ROWS = 32768;
static constexpr int COLS = 1024;
static constexpr long long N_ELEMS = (long long)ROWS * COLS;   // 33,554,432
static constexpr long long N_VEC4  = N_ELEMS / 4;              // 8,388,608
static constexpr int THREADS = 256;
static constexpr int VEC_PER_THREAD = 8;
static constexpr int BLOCKS = (int)(N_VEC4 / (THREADS * VEC_PER_THREAD)); // 4096
static constexpr int COLS_VEC4 = COLS / 4;                     // 256
static_assert(THREADS == COLS_VEC4, "weight-hoist relies on THREADS == COLS/4");

__global__ __launch_bounds__(THREADS)
void diag_weight_kernel(const float4* __restrict__ x,
                        const float4* __restrict__ w,
                        float4* __restrict__ out) {
    const unsigned tid = threadIdx.x;
    // Block covers a contiguous span of THREADS*VEC_PER_THREAD float4s;
    // within the block, iteration i is offset by i*THREADS (coalesced).
    long long base = (long long)blockIdx.x * (THREADS * VEC_PER_THREAD) + tid;

    // One weight vector per thread: column index of every element this thread
    // touches is (base + i*256) mod 256 == tid. Plain load (reused, cacheable).
    const float4 vw = w[tid];

    float4 vx[VEC_PER_THREAD];

    // Front-batch all 8 global loads (streaming hint: no reuse).
#pragma unroll
    for (int i = 0; i < VEC_PER_THREAD; i++) {
        vx[i] = __ldcs(&x[base + (long long)i * THREADS]);
    }

#pragma unroll
    for (int i = 0; i < VEC_PER_THREAD; i++) {
        float4 r;
        r.x = vx[i].x * vw.x;
        r.y = vx[i].y * vw.y;
        r.z = vx[i].z * vw.z;
        r.w = vx[i].w * vw.w;
        __stcs(&out[base + (long long)i * THREADS], r);
    }
}

extern "C" void kernel_launch(void* const* d_in, const int* in_sizes, int n_in,
                              void* d_out, int out_size) {
    const float4* x = (const float4*)d_in[0];   // [32768, 1024] fp32
    const float4* w = (const float4*)d_in[1];   // [1024] fp32
    float4* out = (float4*)d_out;

    diag_weight_kernel<<<BLOCKS, THREADS>>>(x, w, out);
}